// round 3
// baseline (speedup 1.0000x reference)
#include <cuda_runtime.h>

#define VOCAB 87429
#define EDIM  51
#define EP    52          // padded embedding width (13 float4)
#define CCH   39
#define HTOK  8192
#define NJ    38          // 1+2+5+10+20 weight vectors
#define NJP   40          // padded
#define TH    128         // h-tile per block in k1
#define NBH   (HTOK / TH) // 64
#define NCZ   4           // channel chunks: 10,10,10,9
#define SLC   (HTOK * NJP)

#define SM_EMB (TH * EP)      // 6656 floats
#define SM_W   (NJP * EP)     // 2080 floats
#define K1_SMEM_BYTES (2 * (SM_EMB + SM_W) * 4)   // 69888

// scratch (device globals — no allocation allowed)
__device__ float        g_embp[VOCAB * EP];       // padded embedding ~18.2 MB
__device__ float        g_wpk [CCH * NJP * EP];   // packed weights [c][j][e]
__device__ float        g_A   [NCZ * SLC];        // partials, layout [z][j][h]
__device__ unsigned int g_max5[5];

__device__ __forceinline__ void fma2(unsigned long long& d,
                                     unsigned long long a,
                                     unsigned long long b) {
    asm("fma.rn.f32x2 %0, %1, %2, %0;" : "+l"(d) : "l"(a), "l"(b));
}
__device__ __forceinline__ void cpa16(void* dst_smem, const void* src_gmem) {
    unsigned dst = (unsigned)__cvta_generic_to_shared(dst_smem);
    asm volatile("cp.async.ca.shared.global [%0], [%1], 16;\n" :: "r"(dst), "l"(src_gmem));
}
__device__ __forceinline__ void cpa_commit() {
    asm volatile("cp.async.commit_group;\n");
}
__device__ __forceinline__ void cpa_wait1() {
    asm volatile("cp.async.wait_group 1;\n");
}

// ---------------------------------------------------------------------------
// kernel 0a: pad embedding table 51 -> 52 floats/row (float4-friendly gathers)
// ---------------------------------------------------------------------------
__global__ void kpad_emb(const float* __restrict__ emb) {
    int idx = blockIdx.x * blockDim.x + threadIdx.x;
    if (idx >= VOCAB * EP) return;
    int r = idx / EP;
    int e = idx - r * EP;
    g_embp[idx] = (e < EDIM) ? emb[r * EDIM + e] : 0.0f;
}

// ---------------------------------------------------------------------------
// kernel 0b: pack branch conv weights into [c][j][e] padded layout
// ---------------------------------------------------------------------------
__global__ void kpack_w(const float* __restrict__ w0, const float* __restrict__ w1,
                        const float* __restrict__ w2, const float* __restrict__ w3,
                        const float* __restrict__ w4) {
    int idx = blockIdx.x * blockDim.x + threadIdx.x;
    if (idx >= CCH * NJP * EP) return;
    int c   = idx / (NJP * EP);
    int rem = idx - c * (NJP * EP);
    int j   = rem / EP;
    int e   = rem - j * EP;
    float v = 0.0f;
    if (j < NJ && e < EDIM) {
        const float* wp; int kk, dk;
        if      (j < 1)  { wp = w0; kk = 1;  dk = j; }
        else if (j < 3)  { wp = w1; kk = 2;  dk = j - 1; }
        else if (j < 8)  { wp = w2; kk = 5;  dk = j - 3; }
        else if (j < 18) { wp = w3; kk = 10; dk = j - 8; }
        else             { wp = w4; kk = 20; dk = j - 18; }
        v = wp[(c * kk + dk) * EDIM + e];
    }
    g_wpk[idx] = v;
}

// ---------------------------------------------------------------------------
// kernel 1: A_z[j][h] = sum_{c in chunk z} emb[tok[c,h]] . W[c][j]
//   128 threads, 8h x 5j fma.rn.f32x2 register tile, cp.async double-buffered
//   staging (gather latency fully overlapped with compute of previous channel).
// ---------------------------------------------------------------------------
__global__ __launch_bounds__(128, 2) void k1_dots(const int* __restrict__ tokens) {
    extern __shared__ float smem[];
    float* s_emb = smem;                    // [2][SM_EMB]
    float* s_w   = smem + 2 * SM_EMB;       // [2][SM_W]

    const int tid  = threadIdx.x;
    const int h0   = blockIdx.x * TH;
    const int z    = blockIdx.y;
    const int cbeg = z * 10;
    const int nch  = ((cbeg + 10 < CCH) ? 10 : (CCH - cbeg));

    if (blockIdx.x == 0 && z == 0 && tid < 5) g_max5[tid] = 0u;  // k2 runs after

    // preload this thread's token per channel (latency overlapped at startup)
    int tk[10];
    #pragma unroll
    for (int i = 0; i < 10; i++)
        tk[i] = (i < nch) ? tokens[(cbeg + i) * HTOK + h0 + tid] : 0;

    const int u = tid >> 3;   // 0..15
    const int v = tid & 7;    // 0..7

    unsigned long long acc[8][5];
    #pragma unroll
    for (int i = 0; i < 8; i++)
        #pragma unroll
        for (int j = 0; j < 5; j++) acc[i][j] = 0ull;

    // --- staging helper (inlined twice): channel cc -> buffer b ---
    #define STAGE(CC, B) do {                                                  \
        const float* wsrc = &g_wpk[(cbeg + (CC)) * SM_W];                      \
        float* wdst = &s_w[(B) * SM_W];                                        \
        _Pragma("unroll")                                                      \
        for (int q = 0; q < 5; q++) {                                          \
            int idx = tid + q * 128;                                           \
            if (idx < SM_W / 4) cpa16(wdst + idx * 4, wsrc + idx * 4);         \
        }                                                                      \
        const float* esrc = &g_embp[tk[(CC)] * EP];                            \
        float* edst = &s_emb[(B) * SM_EMB + tid * EP];                         \
        _Pragma("unroll")                                                      \
        for (int q = 0; q < 13; q++) cpa16(edst + q * 4, esrc + q * 4);        \
    } while (0)

    STAGE(0, 0);
    cpa_commit();

    int buf = 0;
    for (int cc = 0; cc < nch; cc++) {
        if (cc + 1 < nch) STAGE(cc + 1, buf ^ 1);
        cpa_commit();
        cpa_wait1();          // buffer `buf` (group cc) complete
        __syncthreads();

        const float* se = &s_emb[buf * SM_EMB];
        const float* sw = &s_w[buf * SM_W];
        #pragma unroll
        for (int e4 = 0; e4 < 13; e4++) {
            ulonglong2 ev[8], wv[5];
            #pragma unroll
            for (int i = 0; i < 8; i++)
                ev[i] = *(const ulonglong2*)&se[(u + 16 * i) * EP + e4 * 4];
            #pragma unroll
            for (int j = 0; j < 5; j++)
                wv[j] = *(const ulonglong2*)&sw[(v + 8 * j) * EP + e4 * 4];
            #pragma unroll
            for (int i = 0; i < 8; i++)
                #pragma unroll
                for (int j = 0; j < 5; j++)
                    fma2(acc[i][j], ev[i].x, wv[j].x);
            #pragma unroll
            for (int i = 0; i < 8; i++)
                #pragma unroll
                for (int j = 0; j < 5; j++)
                    fma2(acc[i][j], ev[i].y, wv[j].y);
        }
        __syncthreads();      // all warps done with `buf` before it is restaged
        buf ^= 1;
    }
    #undef STAGE

    // write transposed: A[z][j][h]
    float* Az = &g_A[z * SLC];
    #pragma unroll
    for (int i = 0; i < 8; i++)
        #pragma unroll
        for (int j = 0; j < 5; j++) {
            unsigned long long a = acc[i][j];
            float lo = __uint_as_float((unsigned)(a & 0xffffffffull));
            float hi = __uint_as_float((unsigned)(a >> 32));
            Az[(v + 8 * j) * HTOK + (h0 + u + 16 * i)] = lo + hi;
        }
}

// ---------------------------------------------------------------------------
// kernel 2: per-(h-block, branch) max of relu(conv+b). A is [z][j][h].
//   4 lanes per h (one per z slice), shfl combine, warp+block max, atomicMax.
// ---------------------------------------------------------------------------
__global__ void k2_branch(const float* __restrict__ b0, const float* __restrict__ b1,
                          const float* __restrict__ b2, const float* __restrict__ b3,
                          const float* __restrict__ b4) {
    __shared__ unsigned int sm;
    const int tid = threadIdx.x;       // 256
    const int zl  = tid & 3;
    const int hl  = tid >> 2;          // 0..63
    const int br  = blockIdx.y;
    const int h   = blockIdx.x * 64 + hl;
    if (tid == 0) sm = 0u;
    __syncthreads();

    const int base[5] = {0, 1, 3, 8, 18};
    const int cnt [5] = {1, 2, 5, 10, 20};
    const int k = cnt[br];

    float y = 0.0f;
    if (h <= HTOK - k) {
        const float* Az = g_A + zl * SLC + base[br] * HTOK + h;
        #pragma unroll 5
        for (int d = 0; d < k; d++)
            y += Az[d * (HTOK + 1)];
    }
    y += __shfl_xor_sync(0xffffffffu, y, 1);
    y += __shfl_xor_sync(0xffffffffu, y, 2);

    const float* bp = (br == 0) ? b0 : (br == 1) ? b1 : (br == 2) ? b2
                    : (br == 3) ? b3 : b4;
    float val = (h <= HTOK - k) ? fmaxf(y + *bp, 0.0f) : 0.0f;
    #pragma unroll
    for (int off = 4; off < 32; off <<= 1)
        val = fmaxf(val, __shfl_xor_sync(0xffffffffu, val, off));
    if ((tid & 31) == 0) atomicMax(&sm, __float_as_uint(val));
    __syncthreads();
    if (tid == 0) atomicMax(&g_max5[br], sm);
}

// ---------------------------------------------------------------------------
// kernel 3: 5 -> 8 linear, relu, softmax -> out[8]
// ---------------------------------------------------------------------------
__global__ void k3_head(const float* __restrict__ lin_w, const float* __restrict__ lin_b,
                        float* __restrict__ out) {
    if (threadIdx.x != 0 || blockIdx.x != 0) return;
    float f[5];
    #pragma unroll
    for (int i = 0; i < 5; i++) f[i] = __uint_as_float(g_max5[i]);
    float lg[8], mx = -1e30f;
    #pragma unroll
    for (int o = 0; o < 8; o++) {
        float s = lin_b[o];
        #pragma unroll
        for (int i = 0; i < 5; i++) s += lin_w[o * 5 + i] * f[i];
        s = fmaxf(s, 0.0f);
        lg[o] = s;
        mx = fmaxf(mx, s);
    }
    float den = 0.0f;
    #pragma unroll
    for (int o = 0; o < 8; o++) { lg[o] = expf(lg[o] - mx); den += lg[o]; }
    #pragma unroll
    for (int o = 0; o < 8; o++) out[o] = lg[o] / den;
}

// ---------------------------------------------------------------------------
extern "C" void kernel_launch(void* const* d_in, const int* in_sizes, int n_in,
                              void* d_out, int out_size) {
    const int*   tokens = (const int*)  d_in[0];
    const float* emb    = (const float*)d_in[1];
    const float* lin_w  = (const float*)d_in[2];
    const float* lin_b  = (const float*)d_in[3];
    const float* w0     = (const float*)d_in[4];
    const float* b0     = (const float*)d_in[5];
    const float* w1     = (const float*)d_in[6];
    const float* b1     = (const float*)d_in[7];
    const float* w2     = (const float*)d_in[8];
    const float* b2     = (const float*)d_in[9];
    const float* w3     = (const float*)d_in[10];
    const float* b3     = (const float*)d_in[11];
    const float* w4     = (const float*)d_in[12];
    const float* b4     = (const float*)d_in[13];
    float* out = (float*)d_out;

    static int smem_set = 0;
    if (!smem_set) {
        cudaFuncSetAttribute(k1_dots, cudaFuncAttributeMaxDynamicSharedMemorySize,
                             K1_SMEM_BYTES);
        smem_set = 1;
    }

    kpad_emb<<<(VOCAB * EP + 255) / 256, 256>>>(emb);
    kpack_w <<<(CCH * NJP * EP + 255) / 256, 256>>>(w0, w1, w2, w3, w4);
    k1_dots <<<dim3(NBH, NCZ), 128, K1_SMEM_BYTES>>>(tokens);
    k2_branch<<<dim3(HTOK / 64, 5), 256>>>(b0, b1, b2, b3, b4);
    k3_head <<<1, 32>>>(lin_w, lin_b, out);
}